// round 6
// baseline (speedup 1.0000x reference)
#include <cuda_runtime.h>
#include <cstdint>

#define B_   64
#define T_   2048
#define C_   64
#define H_   256
#define HOR_ 96

// ---------------- scratch (device globals; no runtime allocation) ----------------
__device__ float g_cur[(size_t)B_ * T_ * H_];            // 134 MB
__device__ float g_hcomb[(size_t)B_ * T_ * (C_ + H_)];   // 168 MB
__device__ float g_gx[(size_t)B_ * T_ * 3 * H_];         // 403 MB
__device__ float g_hT[B_ * H_];

// ---------------- generic GEMM: C[M,N] = A[M,K] @ Bw[N,K]^T + bias[N] ----------------
// BM=128, BN=64, BK=16, 256 threads, 8x4 per thread. M%128==0, N%64==0, K%16==0.
__global__ void __launch_bounds__(256, 1)
gemm_abt_kernel(const float* __restrict__ A, const float* __restrict__ Bw,
                const float* __restrict__ bias, float* __restrict__ C,
                int K, int N)
{
    __shared__ float As[16][128];
    __shared__ float Bs[16][64];

    const int tid = threadIdx.x;
    const int tx  = tid & 15;          // n-group (4 cols)
    const int ty  = tid >> 4;          // m-group (8 rows)
    const size_t bm = (size_t)blockIdx.y * 128;
    const int    bn = blockIdx.x * 64;

    float acc[8][4];
#pragma unroll
    for (int i = 0; i < 8; i++)
#pragma unroll
        for (int j = 0; j < 4; j++) acc[i][j] = 0.f;

    const int lr = tid >> 2;           // 0..63
    const int lk = (tid & 3) * 4;      // 0,4,8,12

    for (int kt = 0; kt < K; kt += 16) {
        float4 a0 = *(const float4*)&A[(bm + lr) * (size_t)K + kt + lk];
        float4 a1 = *(const float4*)&A[(bm + lr + 64) * (size_t)K + kt + lk];
        float4 b0 = *(const float4*)&Bw[(size_t)(bn + lr) * K + kt + lk];

        As[lk + 0][lr] = a0.x; As[lk + 1][lr] = a0.y;
        As[lk + 2][lr] = a0.z; As[lk + 3][lr] = a0.w;
        As[lk + 0][lr + 64] = a1.x; As[lk + 1][lr + 64] = a1.y;
        As[lk + 2][lr + 64] = a1.z; As[lk + 3][lr + 64] = a1.w;
        Bs[lk + 0][lr] = b0.x; Bs[lk + 1][lr] = b0.y;
        Bs[lk + 2][lr] = b0.z; Bs[lk + 3][lr] = b0.w;
        __syncthreads();

#pragma unroll
        for (int k = 0; k < 16; k++) {
            float4 x01 = *(const float4*)&As[k][ty * 8];
            float4 x23 = *(const float4*)&As[k][ty * 8 + 4];
            float4 bb  = *(const float4*)&Bs[k][tx * 4];
            float av[8] = {x01.x, x01.y, x01.z, x01.w, x23.x, x23.y, x23.z, x23.w};
            float bv[4] = {bb.x, bb.y, bb.z, bb.w};
#pragma unroll
            for (int i = 0; i < 8; i++)
#pragma unroll
                for (int j = 0; j < 4; j++)
                    acc[i][j] = fmaf(av[i], bv[j], acc[i][j]);
        }
        __syncthreads();
    }

    float4 b4 = *(const float4*)&bias[bn + tx * 4];
#pragma unroll
    for (int i = 0; i < 8; i++) {
        float4 o;
        o.x = acc[i][0] + b4.x; o.y = acc[i][1] + b4.y;
        o.z = acc[i][2] + b4.z; o.w = acc[i][3] + b4.w;
        *(float4*)&C[(bm + ty * 8 + i) * (size_t)N + bn + tx * 4] = o;
    }
}

// ---------------- copy x into hcomb[:, :, 0:64] ----------------
__global__ void copyx_kernel(const float* __restrict__ x, float* __restrict__ hcomb)
{
    int i   = blockIdx.x * 256 + threadIdx.x;   // float4 index over B*T*16
    int row = i >> 4;
    int c4  = i & 15;
    ((float4*)hcomb)[(size_t)row * 80 + c4] = ((const float4*)x)[i];
}

// ---------------- LIF scan: spikes -> hcomb[:, :, 64:320] ----------------
__global__ void lif_kernel(const float* __restrict__ cur, float* __restrict__ hcomb)
{
    int b = blockIdx.x >> 1;
    int h = (blockIdx.x & 1) * 128 + threadIdx.x;
    const float* cp = cur + ((size_t)b * T_) * H_ + h;
    float* sp = hcomb + ((size_t)b * T_) * 320 + 64 + h;

    float mem = 0.f;
#pragma unroll 8
    for (int t = 0; t < T_; t++) {
        float iv = __ldg(cp); cp += H_;
        float reset = (mem > 1.0f) ? 1.0f : 0.0f;
        // mem = 0.9*mem + i - reset  (plain fp32 ops, no FMA contraction)
        mem = __fsub_rn(__fadd_rn(__fmul_rn(0.9f, mem), iv), reset);
        float spk = (mem > 1.0f) ? 1.0f : 0.0f;
        *sp = spk; sp += 320;
    }
}

// ---------------- GRU scan: cluster-of-4 persistent, 2 batches per cluster ----------------
// Each CTA owns 64 output channels j = rank*64 + jl (3 gate rows each), whh slice in smem.
#define GRU_SMEM_FLOATS (3 * 128 * 64 * 2 + 1024 + 1536)  // wt(float2 as 2 floats) + shH + shRed
#define GRU_SMEM_BYTES  (GRU_SMEM_FLOATS * 4)             // 206848

__global__ void __cluster_dims__(4, 1, 1) __launch_bounds__(256, 1)
gru_kernel(const float* __restrict__ gx, const float* __restrict__ whh,
           const float* __restrict__ bhh, float* __restrict__ hT)
{
    extern __shared__ float sm[];
    float2* wt    = (float2*)sm;            // [3][128 k-pairs][64 jl]
    float*  shH   = sm + 49152;             // [2 buf][2 batch][256]
    float*  shRed = sm + 49152 + 1024;      // [3 gate * 2 batch][4 q][64 jl]

    const int tid  = threadIdx.x;
    const int rank = blockIdx.x & 3;
    const int b0   = (blockIdx.x >> 2) * 2;

    // load whh slice, transposed & k-paired: wt[g][k2][jl] = (whh[row][2k2], whh[row][2k2+1])
    for (int idx = tid; idx < 3 * 64 * 128; idx += 256) {
        int rr = idx >> 7;          // 0..191
        int k2 = idx & 127;
        int g  = rr >> 6;
        int jl = rr & 63;
        float2 v = *(const float2*)&whh[((size_t)(g * 256 + rank * 64 + jl)) * 256 + 2 * k2];
        wt[(g * 128 + k2) * 64 + jl] = v;
    }
    for (int idx = tid; idx < 1024; idx += 256) shH[idx] = 0.f;

    const int q  = tid >> 6;        // k-quarter
    const int jl = tid & 63;
    const bool isGate = (tid < 128);
    const int gb = (tid >> 6) & 1;  // batch for gate stage
    const int gj = jl;

    float bh0 = 0.f, bh1 = 0.f, bh2 = 0.f;
    const float* gxp = nullptr;
    if (isGate) {
        bh0 = bhh[0 * 256 + rank * 64 + gj];
        bh1 = bhh[1 * 256 + rank * 64 + gj];
        bh2 = bhh[2 * 256 + rank * 64 + gj];
        gxp = gx + ((size_t)(b0 + gb) * T_) * 768 + rank * 64 + gj;
    }

    asm volatile("barrier.cluster.arrive.aligned;" ::: "memory");
    asm volatile("barrier.cluster.wait.aligned;" ::: "memory");

    const float2* w0p = wt + (0 * 128 + q * 32) * 64 + jl;
    const float2* w1p = wt + (1 * 128 + q * 32) * 64 + jl;
    const float2* w2p = wt + (2 * 128 + q * 32) * 64 + jl;

    int p = 0;
    for (int t = 0; t < T_; t++) {
        float xr = 0.f, xz = 0.f, xn = 0.f;
        if (isGate) {                        // issue early; consumed after dot loop
            xr = __ldg(gxp);
            xz = __ldg(gxp + 256);
            xn = __ldg(gxp + 512);
        }

        const float2* h0p = (const float2*)(shH + p * 512) + q * 32;
        const float2* h1p = (const float2*)(shH + p * 512 + 256) + q * 32;
        float a00 = 0.f, a01 = 0.f, a10 = 0.f, a11 = 0.f, a20 = 0.f, a21 = 0.f;
#pragma unroll
        for (int k2 = 0; k2 < 32; k2++) {
            float2 h0 = h0p[k2];
            float2 h1 = h1p[k2];
            float2 w0 = w0p[(size_t)k2 * 64];
            float2 w1 = w1p[(size_t)k2 * 64];
            float2 w2 = w2p[(size_t)k2 * 64];
            a00 = fmaf(w0.x, h0.x, fmaf(w0.y, h0.y, a00));
            a01 = fmaf(w0.x, h1.x, fmaf(w0.y, h1.y, a01));
            a10 = fmaf(w1.x, h0.x, fmaf(w1.y, h0.y, a10));
            a11 = fmaf(w1.x, h1.x, fmaf(w1.y, h1.y, a11));
            a20 = fmaf(w2.x, h0.x, fmaf(w2.y, h0.y, a20));
            a21 = fmaf(w2.x, h1.x, fmaf(w2.y, h1.y, a21));
        }
        shRed[((0 * 2 + 0) * 4 + q) * 64 + jl] = a00;
        shRed[((0 * 2 + 1) * 4 + q) * 64 + jl] = a01;
        shRed[((1 * 2 + 0) * 4 + q) * 64 + jl] = a10;
        shRed[((1 * 2 + 1) * 4 + q) * 64 + jl] = a11;
        shRed[((2 * 2 + 0) * 4 + q) * 64 + jl] = a20;
        shRed[((2 * 2 + 1) * 4 + q) * 64 + jl] = a21;
        __syncthreads();

        if (isGate) {
            int base0 = ((0 * 2 + gb) * 4) * 64 + gj;
            int base1 = ((1 * 2 + gb) * 4) * 64 + gj;
            int base2 = ((2 * 2 + gb) * 4) * 64 + gj;
            float hr = shRed[base0] + shRed[base0 + 64] + shRed[base0 + 128] + shRed[base0 + 192];
            float hz = shRed[base1] + shRed[base1 + 64] + shRed[base1 + 128] + shRed[base1 + 192];
            float hn = shRed[base2] + shRed[base2 + 64] + shRed[base2 + 128] + shRed[base2 + 192];
            float hold = shH[p * 512 + gb * 256 + rank * 64 + gj];

            float r = 1.f / (1.f + expf(-(xr + hr + bh0)));
            float z = 1.f / (1.f + expf(-(xz + hz + bh1)));
            float n = tanhf(xn + r * (hn + bh2));
            float hnew = (1.f - z) * n + z * hold;

            uint32_t laddr;
            {
                const float* pdst = &shH[(p ^ 1) * 512 + gb * 256 + rank * 64 + gj];
                asm("{ .reg .u64 tt; cvta.to.shared.u64 tt, %1; cvt.u32.u64 %0, tt; }"
                    : "=r"(laddr) : "l"(pdst));
            }
#pragma unroll
            for (int rr = 0; rr < 4; rr++) {   // broadcast h_new to all cluster CTAs
                uint32_t ra;
                asm volatile("mapa.shared::cluster.u32 %0, %1, %2;"
                             : "=r"(ra) : "r"(laddr), "r"(rr));
                asm volatile("st.shared::cluster.f32 [%0], %1;" :: "r"(ra), "f"(hnew));
            }
            if (t == T_ - 1) hT[(b0 + gb) * 256 + rank * 64 + gj] = hnew;
            gxp += 768;
        }

        asm volatile("barrier.cluster.arrive.aligned;" ::: "memory");
        asm volatile("barrier.cluster.wait.aligned;" ::: "memory");
        p ^= 1;
    }
}

// ---------------- head: out[b,o] = hT[b,:] . head_w[o,:] + head_b[o] ----------------
__global__ void head_kernel(const float* __restrict__ hT, const float* __restrict__ W,
                            const float* __restrict__ bias, float* __restrict__ out)
{
    int b = blockIdx.x;
    int o = threadIdx.x;   // 96 threads
    const float* h = hT + b * 256;
    const float* w = W + o * 256;
    float s = bias[o];
#pragma unroll 8
    for (int j = 0; j < 256; j++) s = fmaf(h[j], w[j], s);
    out[b * 96 + o] = s;
}

// ---------------- launch ----------------
extern "C" void kernel_launch(void* const* d_in, const int* in_sizes, int n_in,
                              void* d_out, int out_size)
{
    const float* x        = (const float*)d_in[0];
    const float* snn_w    = (const float*)d_in[1];
    const float* snn_b    = (const float*)d_in[2];
    const float* gru_wih  = (const float*)d_in[3];
    const float* gru_whh  = (const float*)d_in[4];
    const float* gru_bih  = (const float*)d_in[5];
    const float* gru_bhh  = (const float*)d_in[6];
    const float* head_w   = (const float*)d_in[7];
    const float* head_b   = (const float*)d_in[8];
    float* out = (float*)d_out;

    float *cur, *hcomb, *gxb, *hTb;
    cudaGetSymbolAddress((void**)&cur,   g_cur);
    cudaGetSymbolAddress((void**)&hcomb, g_hcomb);
    cudaGetSymbolAddress((void**)&gxb,   g_gx);
    cudaGetSymbolAddress((void**)&hTb,   g_hT);

    cudaFuncSetAttribute(gru_kernel, cudaFuncAttributeMaxDynamicSharedMemorySize,
                         GRU_SMEM_BYTES);

    // 1) cur = x @ snn_w^T + snn_b            [131072,64]x[256,64]^T
    gemm_abt_kernel<<<dim3(H_ / 64, (B_ * T_) / 128), 256>>>(x, snn_w, snn_b, cur, C_, H_);
    // 2) hcomb[:, :, 0:64] = x
    copyx_kernel<<<(B_ * T_ * C_ / 4) / 256, 256>>>(x, hcomb);
    // 3) LIF scan -> hcomb[:, :, 64:320]
    lif_kernel<<<128, 128>>>(cur, hcomb);
    // 4) gx = hcomb @ gru_wih^T + gru_bih     [131072,320]x[768,320]^T
    gemm_abt_kernel<<<dim3(768 / 64, (B_ * T_) / 128), 256>>>(hcomb, gru_wih, gru_bih, gxb,
                                                              C_ + H_, 3 * H_);
    // 5) GRU scan (cluster-of-4 persistent)
    gru_kernel<<<128, 256, GRU_SMEM_BYTES>>>(gxb, gru_whh, gru_bhh, hTb);
    // 6) head
    head_kernel<<<B_, HOR_>>>(hTb, head_w, head_b, out);
}

// round 9
// speedup vs baseline: 1.0190x; 1.0190x over previous
#include <cuda_runtime.h>
#include <cuda_bf16.h>
#include <cstdint>

#define B_   64
#define T_   2048
#define C_   64
#define H_   256
#define HOR_ 96

// ---------------- scratch (device globals; no runtime allocation) ----------------
__device__ float g_cur[(size_t)B_ * T_ * H_];            // 134 MB
__device__ float g_hcomb[(size_t)B_ * T_ * (C_ + H_)];   // 168 MB
__device__ float g_gx[(size_t)B_ * T_ * 3 * H_];         // 403 MB
__device__ float g_hT[B_ * H_];

// ---------------- packed f32x2 helpers (sm_100+ PTX, no 'a' feature needed) ----------------
__device__ __forceinline__ unsigned long long ffma2(unsigned long long a,
                                                    unsigned long long b,
                                                    unsigned long long c) {
    unsigned long long d;
    asm("fma.rn.f32x2 %0, %1, %2, %3;" : "=l"(d) : "l"(a), "l"(b), "l"(c));
    return d;
}
__device__ __forceinline__ float f2x_sum(unsigned long long v) {
    float lo = __uint_as_float((uint32_t)v);
    float hi = __uint_as_float((uint32_t)(v >> 32));
    return lo + hi;
}

// ---------------- f32x2 GEMM: C[M,N] = A[M,K] @ Bw[N,K]^T + bias[N] ----------------
// BM=128, BN=128, BK=16, 256 threads, 8x8 f32x2-k-packed accumulators.
// Requires M%128==0, N%128==0, K%16==0.
#define GSP 18   // padded smem row stride (floats) -> conflict-free LDS.64

__global__ void __launch_bounds__(256, 1)
gemm_f32x2_kernel(const float* __restrict__ A, const float* __restrict__ Bw,
                  const float* __restrict__ bias, float* __restrict__ C,
                  int K, int N)
{
    __shared__ float As[2][128 * GSP];
    __shared__ float Bs[2][128 * GSP];

    const int tid = threadIdx.x;
    const int tx  = tid & 15;          // n lane: cols n0 + tx + 16j
    const int ty  = tid >> 4;          // m lane: rows m0 + ty + 16i
    const size_t m0 = (size_t)blockIdx.y * 128;
    const int    n0 = blockIdx.x * 128;

    // loader mapping: row lr (0..127), 8-float half lh (0 or 8)
    const int lr = tid >> 1;
    const int lh = (tid & 1) * 8;
    const float* ag = A + (m0 + lr) * (size_t)K + lh;
    const float* bg = Bw + (size_t)(n0 + lr) * K + lh;
    const int sOff = lr * GSP + lh;

    unsigned long long acc[8][8];
#pragma unroll
    for (int i = 0; i < 8; i++)
#pragma unroll
        for (int j = 0; j < 8; j++) acc[i][j] = 0ull;

    const int NT = K >> 4;

    // prologue: tile 0 -> stage 0
    {
        float4 a0 = *(const float4*)(ag);
        float4 a1 = *(const float4*)(ag + 4);
        float4 b0 = *(const float4*)(bg);
        float4 b1 = *(const float4*)(bg + 4);
        float* da = &As[0][sOff];
        float* db = &Bs[0][sOff];
        *(float2*)(da + 0) = make_float2(a0.x, a0.y);
        *(float2*)(da + 2) = make_float2(a0.z, a0.w);
        *(float2*)(da + 4) = make_float2(a1.x, a1.y);
        *(float2*)(da + 6) = make_float2(a1.z, a1.w);
        *(float2*)(db + 0) = make_float2(b0.x, b0.y);
        *(float2*)(db + 2) = make_float2(b0.z, b0.w);
        *(float2*)(db + 4) = make_float2(b1.x, b1.y);
        *(float2*)(db + 6) = make_float2(b1.z, b1.w);
    }
    __syncthreads();

    for (int t = 0; t < NT; t++) {
        const int p = t & 1;
        const bool more = (t + 1 < NT);
        float4 na0, na1, nb0, nb1;
        if (more) {
            const float* a2 = ag + (t + 1) * 16;
            const float* b2 = bg + (t + 1) * 16;
            na0 = *(const float4*)(a2);
            na1 = *(const float4*)(a2 + 4);
            nb0 = *(const float4*)(b2);
            nb1 = *(const float4*)(b2 + 4);
        }

        const float* Ab = As[p];
        const float* Bb = Bs[p];
#pragma unroll
        for (int kp = 0; kp < 8; kp++) {
            unsigned long long af[8], bf[8];
#pragma unroll
            for (int i = 0; i < 8; i++)
                af[i] = *(const unsigned long long*)&Ab[(ty + 16 * i) * GSP + 2 * kp];
#pragma unroll
            for (int j = 0; j < 8; j++)
                bf[j] = *(const unsigned long long*)&Bb[(tx + 16 * j) * GSP + 2 * kp];
#pragma unroll
            for (int i = 0; i < 8; i++)
#pragma unroll
                for (int j = 0; j < 8; j++)
                    acc[i][j] = ffma2(af[i], bf[j], acc[i][j]);
        }

        if (more) {
            __syncthreads();
            float* da = &As[p ^ 1][sOff];
            float* db = &Bs[p ^ 1][sOff];
            *(float2*)(da + 0) = make_float2(na0.x, na0.y);
            *(float2*)(da + 2) = make_float2(na0.z, na0.w);
            *(float2*)(da + 4) = make_float2(na1.x, na1.y);
            *(float2*)(da + 6) = make_float2(na1.z, na1.w);
            *(float2*)(db + 0) = make_float2(nb0.x, nb0.y);
            *(float2*)(db + 2) = make_float2(nb0.z, nb0.w);
            *(float2*)(db + 4) = make_float2(nb1.x, nb1.y);
            *(float2*)(db + 6) = make_float2(nb1.z, nb1.w);
            __syncthreads();
        }
    }

    float bj[8];
#pragma unroll
    for (int j = 0; j < 8; j++) bj[j] = __ldg(&bias[n0 + tx + 16 * j]);
#pragma unroll
    for (int i = 0; i < 8; i++) {
        float* cr = C + (m0 + ty + 16 * i) * (size_t)N + n0 + tx;
#pragma unroll
        for (int j = 0; j < 8; j++)
            cr[16 * j] = f2x_sum(acc[i][j]) + bj[j];
    }
}

// ---------------- copy x into hcomb[:, :, 0:64] ----------------
__global__ void copyx_kernel(const float* __restrict__ x, float* __restrict__ hcomb)
{
    int i   = blockIdx.x * 256 + threadIdx.x;   // float4 index over B*T*16
    int row = i >> 4;
    int c4  = i & 15;
    ((float4*)hcomb)[(size_t)row * 80 + c4] = ((const float4*)x)[i];
}

// ---------------- LIF scan: spikes -> hcomb[:, :, 64:320] ----------------
__global__ void lif_kernel(const float* __restrict__ cur, float* __restrict__ hcomb)
{
    int b = blockIdx.x >> 1;
    int h = (blockIdx.x & 1) * 128 + threadIdx.x;
    const float* cp = cur + ((size_t)b * T_) * H_ + h;
    float* sp = hcomb + ((size_t)b * T_) * 320 + 64 + h;

    float mem = 0.f;
#pragma unroll 8
    for (int t = 0; t < T_; t++) {
        float iv = __ldg(cp); cp += H_;
        float reset = (mem > 1.0f) ? 1.0f : 0.0f;
        mem = __fsub_rn(__fadd_rn(__fmul_rn(0.9f, mem), iv), reset);
        float spk = (mem > 1.0f) ? 1.0f : 0.0f;
        *sp = spk; sp += 320;
    }
}

// ---------------- GRU scan: cluster-of-4 persistent, 2 batches per cluster ----------------
#define GRU_SMEM_FLOATS (3 * 128 * 64 * 2 + 1024 + 1536)
#define GRU_SMEM_BYTES  (GRU_SMEM_FLOATS * 4)             // 206848

__global__ void __cluster_dims__(4, 1, 1) __launch_bounds__(256, 1)
gru_kernel(const float* __restrict__ gx, const float* __restrict__ whh,
           const float* __restrict__ bhh, float* __restrict__ hT)
{
    extern __shared__ float smf[];
    float2* wt    = (float2*)smf;           // [3][128 k-pairs][64 jl]
    float*  shH   = smf + 49152;            // [2 buf][2 batch][256]
    float*  shRed = smf + 49152 + 1024;     // [3 gate * 2 batch][4 q][64 jl]

    const int tid  = threadIdx.x;
    const int rank = blockIdx.x & 3;
    const int b0   = (blockIdx.x >> 2) * 2;

    for (int idx = tid; idx < 3 * 64 * 128; idx += 256) {
        int rr = idx >> 7;
        int k2 = idx & 127;
        int g  = rr >> 6;
        int jl = rr & 63;
        float2 v = *(const float2*)&whh[((size_t)(g * 256 + rank * 64 + jl)) * 256 + 2 * k2];
        wt[(g * 128 + k2) * 64 + jl] = v;
    }
    for (int idx = tid; idx < 1024; idx += 256) shH[idx] = 0.f;

    const int q  = tid >> 6;
    const int jl = tid & 63;
    const bool isGate = (tid < 128);
    const int gb = (tid >> 6) & 1;
    const int gj = jl;

    float bh0 = 0.f, bh1 = 0.f, bh2 = 0.f;
    const float* gxp = nullptr;
    if (isGate) {
        bh0 = bhh[0 * 256 + rank * 64 + gj];
        bh1 = bhh[1 * 256 + rank * 64 + gj];
        bh2 = bhh[2 * 256 + rank * 64 + gj];
        gxp = gx + ((size_t)(b0 + gb) * T_) * 768 + rank * 64 + gj;
    }

    asm volatile("barrier.cluster.arrive.aligned;" ::: "memory");
    asm volatile("barrier.cluster.wait.aligned;" ::: "memory");

    const unsigned long long* w0p = (const unsigned long long*)(wt + (0 * 128 + q * 32) * 64 + jl);
    const unsigned long long* w1p = (const unsigned long long*)(wt + (1 * 128 + q * 32) * 64 + jl);
    const unsigned long long* w2p = (const unsigned long long*)(wt + (2 * 128 + q * 32) * 64 + jl);

    int p = 0;
    for (int t = 0; t < T_; t++) {
        float xr = 0.f, xz = 0.f, xn = 0.f;
        if (isGate) {
            xr = __ldg(gxp);
            xz = __ldg(gxp + 256);
            xn = __ldg(gxp + 512);
        }

        const unsigned long long* h0p = (const unsigned long long*)(shH + p * 512) + q * 32;
        const unsigned long long* h1p = (const unsigned long long*)(shH + p * 512 + 256) + q * 32;
        unsigned long long a00 = 0ull, a01 = 0ull, a10 = 0ull, a11 = 0ull, a20 = 0ull, a21 = 0ull;
#pragma unroll
        for (int k2 = 0; k2 < 32; k2++) {
            unsigned long long h0 = h0p[k2];
            unsigned long long h1 = h1p[k2];
            unsigned long long w0 = w0p[(size_t)k2 * 64];
            unsigned long long w1 = w1p[(size_t)k2 * 64];
            unsigned long long w2 = w2p[(size_t)k2 * 64];
            a00 = ffma2(w0, h0, a00);
            a01 = ffma2(w0, h1, a01);
            a10 = ffma2(w1, h0, a10);
            a11 = ffma2(w1, h1, a11);
            a20 = ffma2(w2, h0, a20);
            a21 = ffma2(w2, h1, a21);
        }
        shRed[((0 * 2 + 0) * 4 + q) * 64 + jl] = f2x_sum(a00);
        shRed[((0 * 2 + 1) * 4 + q) * 64 + jl] = f2x_sum(a01);
        shRed[((1 * 2 + 0) * 4 + q) * 64 + jl] = f2x_sum(a10);
        shRed[((1 * 2 + 1) * 4 + q) * 64 + jl] = f2x_sum(a11);
        shRed[((2 * 2 + 0) * 4 + q) * 64 + jl] = f2x_sum(a20);
        shRed[((2 * 2 + 1) * 4 + q) * 64 + jl] = f2x_sum(a21);
        __syncthreads();

        if (isGate) {
            int base0 = ((0 * 2 + gb) * 4) * 64 + gj;
            int base1 = ((1 * 2 + gb) * 4) * 64 + gj;
            int base2 = ((2 * 2 + gb) * 4) * 64 + gj;
            float hr = shRed[base0] + shRed[base0 + 64] + shRed[base0 + 128] + shRed[base0 + 192];
            float hz = shRed[base1] + shRed[base1 + 64] + shRed[base1 + 128] + shRed[base1 + 192];
            float hn = shRed[base2] + shRed[base2 + 64] + shRed[base2 + 128] + shRed[base2 + 192];
            float hold = shH[p * 512 + gb * 256 + rank * 64 + gj];

            float r = 1.f / (1.f + expf(-(xr + hr + bh0)));
            float z = 1.f / (1.f + expf(-(xz + hz + bh1)));
            float n = tanhf(xn + r * (hn + bh2));
            float hnew = (1.f - z) * n + z * hold;

            uint32_t laddr;
            {
                const float* pdst = &shH[(p ^ 1) * 512 + gb * 256 + rank * 64 + gj];
                asm("{ .reg .u64 tt; cvta.to.shared.u64 tt, %1; cvt.u32.u64 %0, tt; }"
                    : "=r"(laddr) : "l"(pdst));
            }
#pragma unroll
            for (int rr = 0; rr < 4; rr++) {
                uint32_t ra;
                asm volatile("mapa.shared::cluster.u32 %0, %1, %2;"
                             : "=r"(ra) : "r"(laddr), "r"(rr));
                asm volatile("st.shared::cluster.f32 [%0], %1;" :: "r"(ra), "f"(hnew));
            }
            if (t == T_ - 1) hT[(b0 + gb) * 256 + rank * 64 + gj] = hnew;
            gxp += 768;
        }

        asm volatile("barrier.cluster.arrive.aligned;" ::: "memory");
        asm volatile("barrier.cluster.wait.aligned;" ::: "memory");
        p ^= 1;
    }
}

// ---------------- head ----------------
__global__ void head_kernel(const float* __restrict__ hT, const float* __restrict__ W,
                            const float* __restrict__ bias, float* __restrict__ out)
{
    int b = blockIdx.x;
    int o = threadIdx.x;   // 96 threads
    const float* h = hT + b * 256;
    const float* w = W + o * 256;
    float s = bias[o];
#pragma unroll 8
    for (int j = 0; j < 256; j++) s = fmaf(h[j], w[j], s);
    out[b * 96 + o] = s;
}

// ---------------- launch ----------------
extern "C" void kernel_launch(void* const* d_in, const int* in_sizes, int n_in,
                              void* d_out, int out_size)
{
    const float* x        = (const float*)d_in[0];
    const float* snn_w    = (const float*)d_in[1];
    const float* snn_b    = (const float*)d_in[2];
    const float* gru_wih  = (const float*)d_in[3];
    const float* gru_whh  = (const float*)d_in[4];
    const float* gru_bih  = (const float*)d_in[5];
    const float* gru_bhh  = (const float*)d_in[6];
    const float* head_w   = (const float*)d_in[7];
    const float* head_b   = (const float*)d_in[8];
    float* out = (float*)d_out;

    float *cur, *hcomb, *gxb, *hTb;
    cudaGetSymbolAddress((void**)&cur,   g_cur);
    cudaGetSymbolAddress((void**)&hcomb, g_hcomb);
    cudaGetSymbolAddress((void**)&gxb,   g_gx);
    cudaGetSymbolAddress((void**)&hTb,   g_hT);

    cudaFuncSetAttribute(gru_kernel, cudaFuncAttributeMaxDynamicSharedMemorySize,
                         GRU_SMEM_BYTES);

    // 1) cur = x @ snn_w^T + snn_b            [131072,64]x[256,64]^T  (f32x2)
    gemm_f32x2_kernel<<<dim3(H_ / 128, (B_ * T_) / 128), 256>>>(x, snn_w, snn_b, cur, C_, H_);
    // 2) hcomb[:, :, 0:64] = x
    copyx_kernel<<<(B_ * T_ * C_ / 4) / 256, 256>>>(x, hcomb);
    // 3) LIF scan -> hcomb[:, :, 64:320]
    lif_kernel<<<128, 128>>>(cur, hcomb);
    // 4) gx = hcomb @ gru_wih^T + gru_bih     [131072,320]x[768,320]^T  (f32x2)
    gemm_f32x2_kernel<<<dim3(768 / 128, (B_ * T_) / 128), 256>>>(hcomb, gru_wih, gru_bih, gxb,
                                                                 C_ + H_, 3 * H_);
    // 5) GRU scan (cluster-of-4 persistent, f32x2 dots)
    gru_kernel<<<128, 256, GRU_SMEM_BYTES>>>(gxb, gru_whh, gru_bhh, hTb);
    // 6) head
    head_kernel<<<B_, HOR_>>>(hTb, head_w, head_b, out);
}